// round 14
// baseline (speedup 1.0000x reference)
#include <cuda_runtime.h>
#include <cuda_bf16.h>
#include <cstdint>

#define N_NODES 100000
#define N_EDGES 1250000
#define D       64
#define NBLK    391             // ceil(N_NODES/256)

// Scratch (no allocs allowed). CUDA zero-initializes device globals.
// Invariant: every kernel_launch invocation leaves g_deg and g_agg zeroed
// (k_norm consumes+clears deg; k_out consumes+clears agg) -> graph replays
// are deterministic without dedicated zeroing kernels.
__device__ float g_agg[(size_t)N_NODES * D];
__device__ int   g_deg[N_NODES];
__device__ float g_norm[N_NODES];

// ---------------------------------------------------------------------------
// K1: degree count, 4 edges/thread, no-return reductions (REDG)
__global__ void k_deg(const int* __restrict__ dst) {
    int t = blockIdx.x * 256 + threadIdx.x;
    if (t >= N_EDGES / 4) return;
    int4 d4 = *reinterpret_cast<const int4*>(dst + t * 4);
    asm volatile("red.global.add.u32 [%0], 1;" :: "l"(&g_deg[d4.x]) : "memory");
    asm volatile("red.global.add.u32 [%0], 1;" :: "l"(&g_deg[d4.y]) : "memory");
    asm volatile("red.global.add.u32 [%0], 1;" :: "l"(&g_deg[d4.z]) : "memory");
    asm volatile("red.global.add.u32 [%0], 1;" :: "l"(&g_deg[d4.w]) : "memory");
}

// K2: norm = clip(deg,1)^-0.5 ; consume-and-clear deg for next replay
__global__ void k_norm() {
    int i = blockIdx.x * 256 + threadIdx.x;
    if (i < N_NODES) {
        int d = g_deg[i];
        g_norm[i] = rsqrtf(fmaxf((float)d, 1.0f));
        g_deg[i] = 0;
    }
}

// K3: edge scatter: agg[dst] += feat[src] * norm[src]
// 16 lanes per edge-group; 4 edges per thread (MLP=4 gathers in flight)
__global__ void k_scatter(const float* __restrict__ feat,
                          const int* __restrict__ src,
                          const int* __restrict__ dst) {
    int t = blockIdx.x * 256 + threadIdx.x;
    int grp = t >> 4;
    int sub = t & 15;
    if (grp >= N_EDGES / 4) return;
    int e0 = grp * 4;
    int4 s4 = *reinterpret_cast<const int4*>(src + e0);
    int4 d4 = *reinterpret_cast<const int4*>(dst + e0);
    int s[4] = {s4.x, s4.y, s4.z, s4.w};
    int d[4] = {d4.x, d4.y, d4.z, d4.w};

    float  nm[4];
    float4 v[4];
#pragma unroll
    for (int i = 0; i < 4; i++) nm[i] = __ldg(&g_norm[s[i]]);
#pragma unroll
    for (int i = 0; i < 4; i++)
        v[i] = *reinterpret_cast<const float4*>(feat + (size_t)s[i] * D + sub * 4);
#pragma unroll
    for (int i = 0; i < 4; i++) {
        float4 w = v[i];
        w.x *= nm[i]; w.y *= nm[i]; w.z *= nm[i]; w.w *= nm[i];
        float* p = g_agg + (size_t)d[i] * D + sub * 4;
        asm volatile("red.global.add.v4.f32 [%0], {%1, %2, %3, %4};"
                     :: "l"(p), "f"(w.x), "f"(w.y), "f"(w.z), "f"(w.w)
                     : "memory");
    }
}

// ---------------------------------------------------------------------------
// K4: out = (agg * norm) @ W^T + bias. Plain C (fmaf), compiler-scheduled.
// 4 threads per node, 16 outputs each (4 float4 accumulators, ~40 regs).
// W in smem, bank-staggered jq chunks (bases at banks {0,24,16,8}) so the
// 4 LDS.128 per k are conflict-free; 'ak' is a conflict-free broadcast LDS.
// 64 nodes per 256-thread block. Also consume-and-clear agg for next replay.
#define OUT_NODES 64
#define OUT_BLKS ((N_NODES + OUT_NODES - 1) / OUT_NODES)   // 1563
#define W_ROW  96                       // floats per k-row: 4 chunks at jq*24
#define A_PAD  65
#define SMEM_OUT_BYTES ((64 * W_ROW + OUT_NODES * A_PAD) * 4)   // 41,216 B

__global__ void __launch_bounds__(256)
k_out(const float* __restrict__ W,
      const float* __restrict__ bias,
      float* __restrict__ out) {
    extern __shared__ float sm[];
    float* w_sm = sm;                       // [64][W_ROW]; chunk jq at +jq*24
    float* a_sm = sm + 64 * W_ROW;          // [64 nodes][A_PAD]
    int tid = threadIdx.x;

    // Stage W: w_sm[k][jq*24 + (j%16)] = W[j][k]
    for (int i = tid; i < 64 * 64; i += 256) {
        int j = i >> 6, k = i & 63;
        w_sm[k * W_ROW + (j >> 4) * 24 + (j & 15)] = W[i];
    }
    // Stage a = agg * norm (and clear agg). 64 nodes x 16 float4 = 1024 float4.
    int nbase = blockIdx.x * OUT_NODES;
#pragma unroll
    for (int it = 0; it < 4; it++) {
        int li = tid + it * 256;
        int nl = li >> 4, k4 = (li & 15) << 2;
        int n = nbase + nl;
        float* ap = a_sm + nl * A_PAD + k4;
        if (n < N_NODES) {
            float4* gp = reinterpret_cast<float4*>(g_agg + (size_t)n * D + k4);
            float4 v = *gp;
            float nm = __ldg(&g_norm[n]);
            *gp = make_float4(0.f, 0.f, 0.f, 0.f);     // clear for next replay
            ap[0] = v.x * nm; ap[1] = v.y * nm; ap[2] = v.z * nm; ap[3] = v.w * nm;
        } else {
            ap[0] = 0.f; ap[1] = 0.f; ap[2] = 0.f; ap[3] = 0.f;
        }
    }
    __syncthreads();

    int nl = tid >> 2;                 // local node 0..63
    int jq = tid & 3;                  // output chunk: j in [jq*16, jq*16+16)

    const float* arow = a_sm + nl * A_PAD;
    const float* wb   = w_sm + jq * 24;

    float4 acc[4];
#pragma unroll
    for (int i = 0; i < 4; i++)
        acc[i] = __ldg(reinterpret_cast<const float4*>(bias) + jq * 4 + i);

#pragma unroll 8
    for (int k = 0; k < 64; k++) {
        float ak = arow[k];
        const float4* wr = reinterpret_cast<const float4*>(wb + k * W_ROW);
#pragma unroll
        for (int i = 0; i < 4; i++) {
            float4 w4 = wr[i];
            acc[i].x = fmaf(ak, w4.x, acc[i].x);
            acc[i].y = fmaf(ak, w4.y, acc[i].y);
            acc[i].z = fmaf(ak, w4.z, acc[i].z);
            acc[i].w = fmaf(ak, w4.w, acc[i].w);
        }
    }

    int n = nbase + nl;
    if (n < N_NODES) {
        float4* o = reinterpret_cast<float4*>(out + (size_t)n * D + jq * 16);
#pragma unroll
        for (int i = 0; i < 4; i++) o[i] = acc[i];
    }
}

// ---------------------------------------------------------------------------
extern "C" void kernel_launch(void* const* d_in, const int* in_sizes, int n_in,
                              void* d_out, int out_size) {
    const float* feat = (const float*)d_in[0];
    const int*   src  = (const int*)d_in[1];
    const int*   dst  = (const int*)d_in[2];
    const float* W    = (const float*)d_in[3];
    const float* bias = (const float*)d_in[4];
    float* out = (float*)d_out;

    static bool attr_set = false;
    if (!attr_set) {
        cudaFuncSetAttribute(k_out, cudaFuncAttributeMaxDynamicSharedMemorySize,
                             SMEM_OUT_BYTES);
        attr_set = true;
    }

    k_deg<<<(N_EDGES / 4 + 255) / 256, 256>>>(dst);
    k_norm<<<NBLK, 256>>>();
    k_scatter<<<(N_EDGES / 4 * 16 + 255) / 256, 256>>>(feat, src, dst);
    k_out<<<OUT_BLKS, 256, SMEM_OUT_BYTES>>>(W, bias, out);
}

// round 17
// speedup vs baseline: 1.8624x; 1.8624x over previous
#include <cuda_runtime.h>
#include <cuda_bf16.h>
#include <cstdint>

#define N_NODES 100000
#define N_EDGES 1250000
#define D       64
#define NBLK    391             // ceil(N_NODES/256)

// Scratch (no allocs allowed). CUDA zero-initializes device globals.
// Invariant: every kernel_launch invocation leaves g_deg and g_agg zeroed
// (k_norm consumes+clears deg; k_out consumes+clears agg) -> graph replays
// are deterministic without dedicated zeroing kernels.
__device__ float g_agg[(size_t)N_NODES * D];
__device__ int   g_deg[N_NODES];
__device__ float g_norm[N_NODES];

// ---------------------------------------------------------------------------
// K1: degree count, 4 edges/thread, no-return reductions (REDG)
__global__ void k_deg(const int* __restrict__ dst) {
    int t = blockIdx.x * 256 + threadIdx.x;
    if (t >= N_EDGES / 4) return;
    int4 d4 = *reinterpret_cast<const int4*>(dst + t * 4);
    asm volatile("red.global.add.u32 [%0], 1;" :: "l"(&g_deg[d4.x]) : "memory");
    asm volatile("red.global.add.u32 [%0], 1;" :: "l"(&g_deg[d4.y]) : "memory");
    asm volatile("red.global.add.u32 [%0], 1;" :: "l"(&g_deg[d4.z]) : "memory");
    asm volatile("red.global.add.u32 [%0], 1;" :: "l"(&g_deg[d4.w]) : "memory");
}

// K2: norm = clip(deg,1)^-0.5 ; consume-and-clear deg for next replay
__global__ void k_norm() {
    int i = blockIdx.x * 256 + threadIdx.x;
    if (i < N_NODES) {
        int d = g_deg[i];
        g_norm[i] = rsqrtf(fmaxf((float)d, 1.0f));
        g_deg[i] = 0;
    }
}

// K3: edge scatter: agg[dst] += feat[src] * norm[src]
// 16 lanes per edge-group; 4 edges per thread (MLP=4 gathers in flight)
__global__ void k_scatter(const float* __restrict__ feat,
                          const int* __restrict__ src,
                          const int* __restrict__ dst) {
    int t = blockIdx.x * 256 + threadIdx.x;
    int grp = t >> 4;
    int sub = t & 15;
    if (grp >= N_EDGES / 4) return;
    int e0 = grp * 4;
    int4 s4 = *reinterpret_cast<const int4*>(src + e0);
    int4 d4 = *reinterpret_cast<const int4*>(dst + e0);
    int s[4] = {s4.x, s4.y, s4.z, s4.w};
    int d[4] = {d4.x, d4.y, d4.z, d4.w};

    float  nm[4];
    float4 v[4];
#pragma unroll
    for (int i = 0; i < 4; i++) nm[i] = __ldg(&g_norm[s[i]]);
#pragma unroll
    for (int i = 0; i < 4; i++)
        v[i] = *reinterpret_cast<const float4*>(feat + (size_t)s[i] * D + sub * 4);
#pragma unroll
    for (int i = 0; i < 4; i++) {
        float4 w = v[i];
        w.x *= nm[i]; w.y *= nm[i]; w.z *= nm[i]; w.w *= nm[i];
        float* p = g_agg + (size_t)d[i] * D + sub * 4;
        asm volatile("red.global.add.v4.f32 [%0], {%1, %2, %3, %4};"
                     :: "l"(p), "f"(w.x), "f"(w.y), "f"(w.z), "f"(w.w)
                     : "memory");
    }
}

// ---------------------------------------------------------------------------
// K4: out = (agg * norm) @ W^T + bias. Register outer-product GEMM.
// Thread tile: 8 nodes x 8 outputs (64 fp32 accumulators). Per k:
// 2 LDS.128 (a, 8-lane broadcast, 4 addrs/warp 32B apart: conflict-free)
// + 2 LDS.128 (w, same addr per tx: broadcast) feed 64 FMAs.
// A_ROW=260 floats -> 1040B row stride, 16B-aligned for LDS.128.
// 256 nodes per 256-thread block. Also consume-and-clear agg for next replay.
#define OUT_NODES 256
#define OUT_BLKS ((N_NODES + OUT_NODES - 1) / OUT_NODES)   // 391
#define A_ROW   260                     // floats per k-row of a_sm (mult of 4!)
#define W_CHUNK 516                     // floats per tx-chunk of w_sm (64*8+4)
#define SMEM_OUT_BYTES ((64 * A_ROW + 8 * W_CHUNK) * 4)    // 83,072 B

__global__ void __launch_bounds__(256, 2)
k_out(const float* __restrict__ W,
      const float* __restrict__ bias,
      float* __restrict__ out) {
    extern __shared__ float sm[];
    float* a_sm = sm;                   // [64 k][A_ROW] : a_sm[k*A_ROW + n]
    float* w_sm = sm + 64 * A_ROW;      // [8 tx][W_CHUNK]: w_sm[tx*W_CHUNK + k*8 + jj]
    int tid = threadIdx.x;

    // Stage W: W[j][k] -> w_sm[(j>>3)*W_CHUNK + k*8 + (j&7)]
    for (int i = tid; i < 64 * 64; i += 256) {
        int j = i >> 6, k = i & 63;
        w_sm[(j >> 3) * W_CHUNK + k * 8 + (j & 7)] = W[i];
    }
    // Stage a = agg * norm, TRANSPOSED to [k][n]; clear agg as we go.
    int nbase = blockIdx.x * OUT_NODES;
#pragma unroll
    for (int it = 0; it < 16; it++) {
        int li = tid + it * 256;            // 4096 float4 = 256 nodes x 16
        int nl = li >> 4, k4 = (li & 15) << 2;
        int n = nbase + nl;
        float4 v = make_float4(0.f, 0.f, 0.f, 0.f);
        if (n < N_NODES) {
            float4* gp = reinterpret_cast<float4*>(g_agg + (size_t)n * D + k4);
            v = *gp;
            float nm = __ldg(&g_norm[n]);
            *gp = make_float4(0.f, 0.f, 0.f, 0.f);     // clear for next replay
            v.x *= nm; v.y *= nm; v.z *= nm; v.w *= nm;
        }
        a_sm[(k4 + 0) * A_ROW + nl] = v.x;
        a_sm[(k4 + 1) * A_ROW + nl] = v.y;
        a_sm[(k4 + 2) * A_ROW + nl] = v.z;
        a_sm[(k4 + 3) * A_ROW + nl] = v.w;
    }
    __syncthreads();

    int tx = tid & 7;                   // output chunk: j in [tx*8, tx*8+8)
    int ty = tid >> 3;                  // node chunk: n in [ty*8, ty*8+8)

    const float* ap = a_sm + ty * 8;
    const float* wp = w_sm + tx * W_CHUNK;

    float4 b0 = __ldg(reinterpret_cast<const float4*>(bias + tx * 8));
    float4 b1 = __ldg(reinterpret_cast<const float4*>(bias + tx * 8 + 4));

    float4 accA[8], accB[8];
#pragma unroll
    for (int i = 0; i < 8; i++) { accA[i] = b0; accB[i] = b1; }

#pragma unroll 4
    for (int k = 0; k < 64; k++) {
        float4 a0 = *reinterpret_cast<const float4*>(ap + k * A_ROW);
        float4 a1 = *reinterpret_cast<const float4*>(ap + k * A_ROW + 4);
        float4 w0 = *reinterpret_cast<const float4*>(wp + k * 8);
        float4 w1 = *reinterpret_cast<const float4*>(wp + k * 8 + 4);
        float av[8] = {a0.x, a0.y, a0.z, a0.w, a1.x, a1.y, a1.z, a1.w};
#pragma unroll
        for (int i = 0; i < 8; i++) {
            accA[i].x = fmaf(av[i], w0.x, accA[i].x);
            accA[i].y = fmaf(av[i], w0.y, accA[i].y);
            accA[i].z = fmaf(av[i], w0.z, accA[i].z);
            accA[i].w = fmaf(av[i], w0.w, accA[i].w);
            accB[i].x = fmaf(av[i], w1.x, accB[i].x);
            accB[i].y = fmaf(av[i], w1.y, accB[i].y);
            accB[i].z = fmaf(av[i], w1.z, accB[i].z);
            accB[i].w = fmaf(av[i], w1.w, accB[i].w);
        }
    }

#pragma unroll
    for (int i = 0; i < 8; i++) {
        int n = nbase + ty * 8 + i;
        if (n < N_NODES) {
            float4* o = reinterpret_cast<float4*>(out + (size_t)n * D + tx * 8);
            o[0] = accA[i];
            o[1] = accB[i];
        }
    }
}

// ---------------------------------------------------------------------------
extern "C" void kernel_launch(void* const* d_in, const int* in_sizes, int n_in,
                              void* d_out, int out_size) {
    const float* feat = (const float*)d_in[0];
    const int*   src  = (const int*)d_in[1];
    const int*   dst  = (const int*)d_in[2];
    const float* W    = (const float*)d_in[3];
    const float* bias = (const float*)d_in[4];
    float* out = (float*)d_out;

    static bool attr_set = false;
    if (!attr_set) {
        cudaFuncSetAttribute(k_out, cudaFuncAttributeMaxDynamicSharedMemorySize,
                             SMEM_OUT_BYTES);
        attr_set = true;
    }

    k_deg<<<(N_EDGES / 4 + 255) / 256, 256>>>(dst);
    k_norm<<<NBLK, 256>>>();
    k_scatter<<<(N_EDGES / 4 * 16 + 255) / 256, 256>>>(feat, src, dst);
    k_out<<<OUT_BLKS, 256, SMEM_OUT_BYTES>>>(W, bias, out);
}